// round 15
// baseline (speedup 1.0000x reference)
#include <cuda_runtime.h>
#include <cuda_fp16.h>
#include <cstdint>
#include <cstddef>

#define N_NEWS 100000
#define N_ENT  50000
#define N_TOP  2000
#define DIM    128
#define KDIM   384   // 3*DIM
#define HIDN   512
#define OUTD   128
#define MAX_EDGES 1600000
#define NTOT2  (2 * N_NEWS)
#define SCAN_BLOCKS ((NTOT2 + 1023) / 1024)   // 196

// ---------------- scratch (__device__ globals: allocation-free rule) -------
// g_cnt is zero at module load; scan3 re-zeroes it every run (replay-safe).
__device__ int g_cnt[NTOT2];
__device__ int g_deg[NTOT2];
__device__ int g_rowstart[NTOT2];
__device__ int g_cursor[NTOT2];
__device__ int g_bsum[256];
__device__ int g_csr_col[2 * MAX_EDGES];

__device__ __half g_entf16[(size_t)N_ENT * DIM];
__device__ __half g_topf16[(size_t)N_TOP * DIM];

__device__ __half g_X[(size_t)N_NEWS * KDIM];
__device__ __half g_H[(size_t)N_NEWS * HIDN];
__device__ __half g_W1t[(size_t)HIDN * KDIM];   // [N=512][K=384]
__device__ __half g_W2t[(size_t)OUTD * HIDN];   // [N=128][K=512]

// ---------------- helpers --------------------------------------------------
__device__ __forceinline__ uint32_t smem_to_u32(const void* p) {
    uint32_t a;
    asm("{ .reg .u64 t; cvta.to.shared.u64 t, %1; cvt.u32.u64 %0, t; }"
        : "=r"(a) : "l"(p));
    return a;
}

__device__ __forceinline__ void ldsm_x4(uint32_t* r, uint32_t addr) {
    asm volatile("ldmatrix.sync.aligned.m8n8.x4.shared.b16 {%0,%1,%2,%3}, [%4];"
                 : "=r"(r[0]), "=r"(r[1]), "=r"(r[2]), "=r"(r[3]) : "r"(addr));
}
__device__ __forceinline__ void mma_fp16(float* d, const uint32_t* a,
                                         const uint32_t* b) {
    asm volatile(
        "mma.sync.aligned.m16n8k16.row.col.f32.f16.f16.f32 "
        "{%0,%1,%2,%3}, {%4,%5,%6,%7}, {%8,%9}, {%0,%1,%2,%3};"
        : "+f"(d[0]), "+f"(d[1]), "+f"(d[2]), "+f"(d[3])
        : "r"(a[0]), "r"(a[1]), "r"(a[2]), "r"(a[3]), "r"(b[0]), "r"(b[1]));
}

__device__ __forceinline__ void cpa16(uint32_t s, const void* g, int valid) {
    asm volatile("cp.async.cg.shared.global [%0], [%1], 16, %2;"
                 :: "r"(s), "l"(g), "r"(valid ? 16 : 0) : "memory");
}
#define CP_COMMIT() asm volatile("cp.async.commit_group;" ::: "memory")
#define CP_WAIT(n)  asm volatile("cp.async.wait_group %0;" :: "n"(n) : "memory")

// swizzled byte offset inside a [128 rows x 128B] tile
__device__ __forceinline__ uint32_t sw_off(int row, int chunk16) {
    return (uint32_t)row * 128u + (uint32_t)((chunk16 ^ (row & 7)) << 4);
}

// ==================== launch 1: setup ======================================
__global__ void setup_kernel(const float* __restrict__ W1,
                             const float* __restrict__ W2,
                             const int* __restrict__ ent_row, int n_ent,
                             const int* __restrict__ top_row, int n_top,
                             const float* __restrict__ entf,
                             const float* __restrict__ topf,
                             int b1e, int b2e, int bhe, int bte, int bfe) {
    int b = blockIdx.x;
    if (b < b1e) {
        int idx = b * 256 + threadIdx.x;
        if (idx < KDIM * HIDN) {
            int k = idx / HIDN, n = idx - k * HIDN;
            g_W1t[(size_t)n * KDIM + k] = __float2half_rn(W1[idx]);
        }
    } else if (b < b2e) {
        int idx = (b - b1e) * 256 + threadIdx.x;
        if (idx < HIDN * OUTD) {
            int k = idx / OUTD, n = idx - k * OUTD;
            g_W2t[(size_t)n * HIDN + k] = __float2half_rn(W2[idx]);
        }
    } else if (b < bhe) {
        int i = (b - b2e) * 256 + threadIdx.x;
        if (i < n_ent) atomicAdd(&g_cnt[ent_row[i]], 1);
    } else if (b < bte) {
        int i = (b - bhe) * 256 + threadIdx.x;
        if (i < n_top) atomicAdd(&g_cnt[N_NEWS + top_row[i]], 1);
    } else if (b < bfe) {
        size_t i = ((size_t)(b - bte) * 256 + threadIdx.x) * 8;
        if (i < (size_t)N_ENT * DIM) {
            float4 f0 = *reinterpret_cast<const float4*>(entf + i);
            float4 f1 = *reinterpret_cast<const float4*>(entf + i + 4);
            __half h[8];
            h[0] = __float2half_rn(f0.x); h[1] = __float2half_rn(f0.y);
            h[2] = __float2half_rn(f0.z); h[3] = __float2half_rn(f0.w);
            h[4] = __float2half_rn(f1.x); h[5] = __float2half_rn(f1.y);
            h[6] = __float2half_rn(f1.z); h[7] = __float2half_rn(f1.w);
            *reinterpret_cast<uint4*>(&g_entf16[i]) = *reinterpret_cast<uint4*>(h);
        }
    } else {
        size_t i = ((size_t)(b - bfe) * 256 + threadIdx.x) * 8;
        if (i < (size_t)N_TOP * DIM) {
            float4 f0 = *reinterpret_cast<const float4*>(topf + i);
            float4 f1 = *reinterpret_cast<const float4*>(topf + i + 4);
            __half h[8];
            h[0] = __float2half_rn(f0.x); h[1] = __float2half_rn(f0.y);
            h[2] = __float2half_rn(f0.z); h[3] = __float2half_rn(f0.w);
            h[4] = __float2half_rn(f1.x); h[5] = __float2half_rn(f1.y);
            h[6] = __float2half_rn(f1.z); h[7] = __float2half_rn(f1.w);
            *reinterpret_cast<uint4*>(&g_topf16[i]) = *reinterpret_cast<uint4*>(h);
        }
    }
}

// ==================== launches 2-3: parallel scan ==========================
__global__ void scan1_kernel() {
    __shared__ int sh[256];
    int t = threadIdx.x, b = blockIdx.x;
    int base = b * 1024 + t * 4;
    int v0 = 0, v1 = 0, v2 = 0, v3 = 0;
    if (base + 0 < NTOT2) { v0 = g_cnt[base + 0]; g_deg[base + 0] = v0; }
    if (base + 1 < NTOT2) { v1 = g_cnt[base + 1]; g_deg[base + 1] = v1; }
    if (base + 2 < NTOT2) { v2 = g_cnt[base + 2]; g_deg[base + 2] = v2; }
    if (base + 3 < NTOT2) { v3 = g_cnt[base + 3]; g_deg[base + 3] = v3; }
    sh[t] = v0 + v1 + v2 + v3;
    __syncthreads();
    #pragma unroll
    for (int off = 1; off < 256; off <<= 1) {
        int x = 0;
        if (t >= off) x = sh[t - off];
        __syncthreads();
        if (t >= off) sh[t] += x;
        __syncthreads();
    }
    int run = (t > 0) ? sh[t - 1] : 0;
    if (base + 0 < NTOT2) g_rowstart[base + 0] = run; run += v0;
    if (base + 1 < NTOT2) g_rowstart[base + 1] = run; run += v1;
    if (base + 2 < NTOT2) g_rowstart[base + 2] = run; run += v2;
    if (base + 3 < NTOT2) g_rowstart[base + 3] = run;
    if (t == 255) g_bsum[b] = sh[255];
}

// scan3: redundant block-sum scan per block + offsets + cursors + cnt reset
__global__ void scan3_kernel() {
    __shared__ int sh[256];
    int t = threadIdx.x;
    int v = (t < SCAN_BLOCKS) ? g_bsum[t] : 0;
    sh[t] = v;
    __syncthreads();
    #pragma unroll
    for (int off = 1; off < 256; off <<= 1) {
        int x = 0;
        if (t >= off) x = sh[t - off];
        __syncthreads();
        if (t >= off) sh[t] += x;
        __syncthreads();
    }
    int i = blockIdx.x * blockDim.x + t;
    if (i < NTOT2) {
        int bb = i >> 10;
        int off = (bb > 0) ? sh[bb - 1] : 0;
        int r = g_rowstart[i] + off;
        g_rowstart[i] = r;
        g_cursor[i] = r;
        g_cnt[i] = 0;
    }
}

// ==================== launch 4: fill (4 edges/thread, MLP=4) ===============
__device__ __forceinline__ void fill_batch(const int* __restrict__ row,
                                           const int* __restrict__ col,
                                           int n, int cbase, int blk) {
    int base = blk * 1024 + threadIdx.x;
    int r[4], cc[4], p[4];
    #pragma unroll
    for (int s = 0; s < 4; s++) {
        int i = base + s * 256;
        if (i < n) { r[s] = row[i]; cc[s] = col[i]; } else r[s] = -1;
    }
    #pragma unroll
    for (int s = 0; s < 4; s++)
        if (r[s] >= 0) p[s] = atomicAdd(&g_cursor[cbase + r[s]], 1);
    #pragma unroll
    for (int s = 0; s < 4; s++)
        if (r[s] >= 0) g_csr_col[p[s]] = cc[s];
}

__global__ void fill_both_kernel(const int* __restrict__ ent_row,
                                 const int* __restrict__ ent_col, int n_ent,
                                 const int* __restrict__ top_row,
                                 const int* __restrict__ top_col, int n_top,
                                 int be) {
    int b = blockIdx.x;
    if (b < be)
        fill_batch(ent_row, ent_col, n_ent, 0, b);
    else
        fill_batch(top_row, top_col, n_top, N_NEWS, b - be);
}

// ==================== launch 5: gather (one warp per news row) =============
__device__ __forceinline__ void store_h4(int r, int colb, float4 v) {
    __half h[4];
    h[0] = __float2half_rn(v.x);
    h[1] = __float2half_rn(v.y);
    h[2] = __float2half_rn(v.z);
    h[3] = __float2half_rn(v.w);
    *reinterpret_cast<uint2*>(&g_X[(size_t)r * KDIM + colb]) =
        *reinterpret_cast<uint2*>(h);
}

__device__ __forceinline__ void agg_part16(const __half* __restrict__ feats,
                                           int s, int c, int r, int colb,
                                           int lane) {
    float a0 = 0.f, a1 = 0.f, a2 = 0.f, a3 = 0.f;
    const uint2* f2 = reinterpret_cast<const uint2*>(feats);
    int j = 0;
    // 4-edge unroll: 4 independent gathers in flight, 1 fp16 add level
    for (; j + 4 <= c; j += 4) {
        int c0 = g_csr_col[s + j];
        int c1 = g_csr_col[s + j + 1];
        int c2 = g_csr_col[s + j + 2];
        int c3 = g_csr_col[s + j + 3];
        uint2 u0 = f2[(size_t)c0 * 32 + lane];
        uint2 u1 = f2[(size_t)c1 * 32 + lane];
        uint2 u2 = f2[(size_t)c2 * 32 + lane];
        uint2 u3 = f2[(size_t)c3 * 32 + lane];
        __half2 s0 = __hadd2(*reinterpret_cast<__half2*>(&u0.x),
                             *reinterpret_cast<__half2*>(&u1.x));
        __half2 s1 = __hadd2(*reinterpret_cast<__half2*>(&u0.y),
                             *reinterpret_cast<__half2*>(&u1.y));
        __half2 s2 = __hadd2(*reinterpret_cast<__half2*>(&u2.x),
                             *reinterpret_cast<__half2*>(&u3.x));
        __half2 s3 = __hadd2(*reinterpret_cast<__half2*>(&u2.y),
                             *reinterpret_cast<__half2*>(&u3.y));
        float2 p0 = __half22float2(s0);
        float2 p1 = __half22float2(s1);
        float2 q0 = __half22float2(s2);
        float2 q1 = __half22float2(s3);
        a0 += p0.x + q0.x; a1 += p0.y + q0.y;
        a2 += p1.x + q1.x; a3 += p1.y + q1.y;
    }
    if (j + 2 <= c) {
        int c0 = g_csr_col[s + j];
        int c1 = g_csr_col[s + j + 1];
        uint2 u0 = f2[(size_t)c0 * 32 + lane];
        uint2 u1 = f2[(size_t)c1 * 32 + lane];
        __half2 s0 = __hadd2(*reinterpret_cast<__half2*>(&u0.x),
                             *reinterpret_cast<__half2*>(&u1.x));
        __half2 s1 = __hadd2(*reinterpret_cast<__half2*>(&u0.y),
                             *reinterpret_cast<__half2*>(&u1.y));
        float2 p0 = __half22float2(s0);
        float2 p1 = __half22float2(s1);
        a0 += p0.x; a1 += p0.y; a2 += p1.x; a3 += p1.y;
        j += 2;
    }
    if (j < c) {
        int c0 = g_csr_col[s + j];
        uint2 u0 = f2[(size_t)c0 * 32 + lane];
        float2 p0 = __half22float2(*reinterpret_cast<__half2*>(&u0.x));
        float2 p1 = __half22float2(*reinterpret_cast<__half2*>(&u0.y));
        a0 += p0.x; a1 += p0.y; a2 += p1.x; a3 += p1.y;
    }
    float inv = 1.0f / ((float)c + 1e-8f);
    float4 v = make_float4(a0 * inv, a1 * inv, a2 * inv, a3 * inv);
    store_h4(r, colb, v);
}

__global__ __launch_bounds__(256) void gather_kernel(
    const float* __restrict__ news) {
    int gw   = (blockIdx.x * blockDim.x + threadIdx.x) >> 5;
    int lane = threadIdx.x & 31;
    if (gw >= N_NEWS) return;
    float4 v = reinterpret_cast<const float4*>(news)[(size_t)gw * 32 + lane];
    store_h4(gw, lane * 4, v);
    agg_part16(g_entf16, g_rowstart[gw], g_deg[gw], gw, 128 + lane * 4, lane);
    agg_part16(g_topf16, g_rowstart[N_NEWS + gw], g_deg[N_NEWS + gw], gw,
               256 + lane * 4, lane);
}

// ==================== GEMM: cp.async 2-stage, K64, fp16xfp16 ===============
#define TILE_BYTES 16384
#define STAGE_B    (2 * TILE_BYTES)
#define GEMM_SMEM  (2 * STAGE_B)

template <bool TANH, bool HALF_OUT>
__global__ __launch_bounds__(256, 2) void gemm_mma_kernel(
    const __half* __restrict__ A, const __half* __restrict__ Bh,
    const float* __restrict__ bias,
    float* __restrict__ outF, __half* __restrict__ outH,
    int M, int Ntot, int Kfull) {
    extern __shared__ __align__(1024) char smem[];
    const uint32_t sbase = smem_to_u32(smem);

    const int tid  = threadIdx.x;
    const int wid  = tid >> 5;
    const int lane = tid & 31;
    const int wm   = wid & 1;
    const int wn   = wid >> 1;
    const int m0   = blockIdx.y * 128;
    const int n0   = blockIdx.x * 128;

    float acc[4][4][4] = {};

    const int lrow = tid >> 1;
    const int lseg = (tid & 1) * 4;
    const int gr   = m0 + lrow;
    const int a_ok = gr < M;
    const size_t a_base = (size_t)gr * Kfull + lseg * 8;
    const size_t b_base = (size_t)(n0 + lrow) * Kfull + lseg * 8;

    const int a_row = (lane & 7) + ((lane >> 3) & 1) * 8;
    const int a_ch  = lane >> 4;
    const int b_row = (lane & 7) + ((lane >> 4) & 1) * 8;
    const int b_ch  = (lane >> 3) & 1;

    const int n_chunks = Kfull >> 6;

    auto prefetch = [&](int ch) {
        const int k0 = ch << 6;
        const uint32_t sb = sbase + (ch & 1) * STAGE_B;
        const __half* pa = A + a_base + k0;
        const __half* pb = Bh + b_base + k0;
        #pragma unroll
        for (int s = 0; s < 4; s++) {
            uint32_t so = sw_off(lrow, lseg + s);
            cpa16(sb + so,              pa + s * 8, a_ok);
            cpa16(sb + TILE_BYTES + so, pb + s * 8, 1);
        }
        CP_COMMIT();
    };

    prefetch(0);
    for (int ch = 0; ch < n_chunks; ch++) {
        if (ch + 1 < n_chunks) {
            prefetch(ch + 1);
            CP_WAIT(1);
        } else {
            CP_WAIT(0);
        }
        __syncthreads();

        const uint32_t st = sbase + (ch & 1) * STAGE_B;
        #pragma unroll
        for (int kk = 0; kk < 4; kk++) {
            uint32_t afrag[4][4];
            uint32_t bhf[2][4];
            #pragma unroll
            for (int g2 = 0; g2 < 2; g2++) {
                int nr = wn * 32 + g2 * 16 + b_row;
                ldsm_x4(bhf[g2], st + TILE_BYTES + sw_off(nr, 2 * kk + b_ch));
            }
            #pragma unroll
            for (int mi = 0; mi < 4; mi++) {
                int mr = wm * 64 + mi * 16 + a_row;
                ldsm_x4(afrag[mi], st + sw_off(mr, 2 * kk + a_ch));
            }
            #pragma unroll
            for (int mi = 0; mi < 4; mi++)
                #pragma unroll
                for (int ni = 0; ni < 4; ni++)
                    mma_fp16(acc[mi][ni], afrag[mi],
                             &bhf[ni >> 1][(ni & 1) * 2]);
        }
        __syncthreads();
    }

    const int g = lane >> 2;
    const int q = lane & 3;
    #pragma unroll
    for (int mi = 0; mi < 4; mi++) {
        #pragma unroll
        for (int ni = 0; ni < 4; ni++) {
            int col = n0 + wn * 32 + ni * 8 + q * 2;
            float bia0 = bias[col], bia1 = bias[col + 1];
            #pragma unroll
            for (int half = 0; half < 2; half++) {
                int gm = m0 + wm * 64 + mi * 16 + g + half * 8;
                if (gm >= M) continue;
                float v0 = acc[mi][ni][half * 2 + 0] + bia0;
                float v1 = acc[mi][ni][half * 2 + 1] + bia1;
                if (TANH) { v0 = tanhf(v0); v1 = tanhf(v1); }
                size_t o = (size_t)gm * Ntot + col;
                if (HALF_OUT) {
                    *reinterpret_cast<__half2*>(&outH[o]) =
                        __halves2half2(__float2half_rn(v0), __float2half_rn(v1));
                } else {
                    *reinterpret_cast<float2*>(&outF[o]) = make_float2(v0, v1);
                }
            }
        }
    }
}

// ---------------------------------------------------------------------------
extern "C" void kernel_launch(void* const* d_in, const int* in_sizes, int n_in,
                              void* d_out, int out_size) {
    const float* news    = (const float*)d_in[0];
    const float* entf    = (const float*)d_in[1];
    const float* topf    = (const float*)d_in[2];
    const int*   ent_row = (const int*)d_in[3];
    const int*   ent_col = (const int*)d_in[4];
    const int*   top_row = (const int*)d_in[5];
    const int*   top_col = (const int*)d_in[6];
    const float* W1      = (const float*)d_in[7];
    const float* b1      = (const float*)d_in[8];
    const float* W2      = (const float*)d_in[9];
    const float* b2      = (const float*)d_in[10];
    float* out = (float*)d_out;
    int n_ent = in_sizes[3];
    int n_top = in_sizes[5];

    void *p_x, *p_h, *p_w1, *p_w2;
    cudaGetSymbolAddress(&p_x, g_X);
    cudaGetSymbolAddress(&p_h, g_H);
    cudaGetSymbolAddress(&p_w1, g_W1t);
    cudaGetSymbolAddress(&p_w2, g_W2t);

    cudaFuncSetAttribute(gemm_mma_kernel<true, true>,
                         cudaFuncAttributeMaxDynamicSharedMemorySize, GEMM_SMEM);
    cudaFuncSetAttribute(gemm_mma_kernel<false, false>,
                         cudaFuncAttributeMaxDynamicSharedMemorySize, GEMM_SMEM);

    // launch 1: setup (weight prep + hists + fp16 feature conversion)
    {
        int b1e = (KDIM * HIDN + 255) / 256;
        int b2e = b1e + (HIDN * OUTD + 255) / 256;
        int bhe = b2e + (n_ent + 255) / 256;
        int bte = bhe + (n_top + 255) / 256;
        int bfe = bte + (N_ENT * DIM / 8 + 255) / 256;
        int btot = bfe + (N_TOP * DIM / 8 + 255) / 256;
        setup_kernel<<<btot, 256>>>(W1, W2, ent_row, n_ent, top_row, n_top,
                                    entf, topf, b1e, b2e, bhe, bte, bfe);
    }
    // launches 2-3: parallel scan
    scan1_kernel<<<SCAN_BLOCKS, 256>>>();
    scan3_kernel<<<(NTOT2 + 255) / 256, 256>>>();
    // launch 4: fill (4 edges/thread)
    {
        int be = (n_ent + 1023) / 1024;
        int btot = be + (n_top + 1023) / 1024;
        fill_both_kernel<<<btot, 256>>>(ent_row, ent_col, n_ent,
                                        top_row, top_col, n_top, be);
    }
    // launch 5: gather -> X (fp16)
    {
        int blocks = (N_NEWS * 32 + 255) / 256;
        gather_kernel<<<blocks, 256>>>(news);
    }

    const int m_tiles = (N_NEWS + 127) / 128;  // 782

    // launch 6: GEMM1  H = tanh(X @ W1 + b1)
    {
        dim3 grid(HIDN / 128, m_tiles);
        gemm_mma_kernel<true, true><<<grid, 256, GEMM_SMEM>>>(
            (const __half*)p_x, (const __half*)p_w1,
            b1, nullptr, (__half*)p_h,
            N_NEWS, HIDN, KDIM);
    }
    // launch 7: GEMM2  out = H @ W2 + b2
    {
        dim3 grid(OUTD / 128, m_tiles);
        gemm_mma_kernel<false, false><<<grid, 256, GEMM_SMEM>>>(
            (const __half*)p_h, (const __half*)p_w2,
            b2, out, nullptr,
            N_NEWS, OUTD, HIDN);
    }
}

// round 16
// speedup vs baseline: 1.0126x; 1.0126x over previous
#include <cuda_runtime.h>
#include <cuda_fp16.h>
#include <cstdint>
#include <cstddef>

#define N_NEWS 100000
#define N_ENT  50000
#define N_TOP  2000
#define DIM    128
#define KDIM   384   // 3*DIM
#define HIDN   512
#define OUTD   128
#define MAX_EDGES 1600000
#define NTOT2  (2 * N_NEWS)
#define SCAN_BLOCKS ((NTOT2 + 1023) / 1024)   // 196

// ---------------- scratch (__device__ globals: allocation-free rule) -------
// g_cnt is zero at module load; scan3 re-zeroes it every run (replay-safe).
__device__ int g_cnt[NTOT2];
__device__ int g_deg[NTOT2];
__device__ int g_rowstart[NTOT2];
__device__ int g_bsum[256];
__device__ int g_rank[2 * MAX_EDGES];     // within-row rank per edge
__device__ int g_csr_col[2 * MAX_EDGES];

__device__ __half g_entf16[(size_t)N_ENT * DIM];
__device__ __half g_topf16[(size_t)N_TOP * DIM];

__device__ __half g_X[(size_t)N_NEWS * KDIM];
__device__ __half g_H[(size_t)N_NEWS * HIDN];
__device__ __half g_W1t[(size_t)HIDN * KDIM];   // [N=512][K=384]
__device__ __half g_W2t[(size_t)OUTD * HIDN];   // [N=128][K=512]

// ---------------- helpers --------------------------------------------------
__device__ __forceinline__ uint32_t smem_to_u32(const void* p) {
    uint32_t a;
    asm("{ .reg .u64 t; cvta.to.shared.u64 t, %1; cvt.u32.u64 %0, t; }"
        : "=r"(a) : "l"(p));
    return a;
}

__device__ __forceinline__ void ldsm_x4(uint32_t* r, uint32_t addr) {
    asm volatile("ldmatrix.sync.aligned.m8n8.x4.shared.b16 {%0,%1,%2,%3}, [%4];"
                 : "=r"(r[0]), "=r"(r[1]), "=r"(r[2]), "=r"(r[3]) : "r"(addr));
}
__device__ __forceinline__ void mma_fp16(float* d, const uint32_t* a,
                                         const uint32_t* b) {
    asm volatile(
        "mma.sync.aligned.m16n8k16.row.col.f32.f16.f16.f32 "
        "{%0,%1,%2,%3}, {%4,%5,%6,%7}, {%8,%9}, {%0,%1,%2,%3};"
        : "+f"(d[0]), "+f"(d[1]), "+f"(d[2]), "+f"(d[3])
        : "r"(a[0]), "r"(a[1]), "r"(a[2]), "r"(a[3]), "r"(b[0]), "r"(b[1]));
}

__device__ __forceinline__ void cpa16(uint32_t s, const void* g, int valid) {
    asm volatile("cp.async.cg.shared.global [%0], [%1], 16, %2;"
                 :: "r"(s), "l"(g), "r"(valid ? 16 : 0) : "memory");
}
#define CP_COMMIT() asm volatile("cp.async.commit_group;" ::: "memory")
#define CP_WAIT(n)  asm volatile("cp.async.wait_group %0;" :: "n"(n) : "memory")

// swizzled byte offset inside a [128 rows x 128B] tile
__device__ __forceinline__ uint32_t sw_off(int row, int chunk16) {
    return (uint32_t)row * 128u + (uint32_t)((chunk16 ^ (row & 7)) << 4);
}

// ==================== launch 1: setup ======================================
// weight prep + histograms (saving within-row rank) + fp16 feature convert
__global__ void setup_kernel(const float* __restrict__ W1,
                             const float* __restrict__ W2,
                             const int* __restrict__ ent_row, int n_ent,
                             const int* __restrict__ top_row, int n_top,
                             const float* __restrict__ entf,
                             const float* __restrict__ topf,
                             int b1e, int b2e, int bhe, int bte, int bfe) {
    int b = blockIdx.x;
    if (b < b1e) {
        int idx = b * 256 + threadIdx.x;
        if (idx < KDIM * HIDN) {
            int k = idx / HIDN, n = idx - k * HIDN;
            g_W1t[(size_t)n * KDIM + k] = __float2half_rn(W1[idx]);
        }
    } else if (b < b2e) {
        int idx = (b - b1e) * 256 + threadIdx.x;
        if (idx < HIDN * OUTD) {
            int k = idx / OUTD, n = idx - k * OUTD;
            g_W2t[(size_t)n * HIDN + k] = __float2half_rn(W2[idx]);
        }
    } else if (b < bhe) {
        int i = (b - b2e) * 256 + threadIdx.x;
        if (i < n_ent) {
            int p = atomicAdd(&g_cnt[ent_row[i]], 1);
            g_rank[i] = p;
        }
    } else if (b < bte) {
        int i = (b - bhe) * 256 + threadIdx.x;
        if (i < n_top) {
            int p = atomicAdd(&g_cnt[N_NEWS + top_row[i]], 1);
            g_rank[MAX_EDGES + i] = p;
        }
    } else if (b < bfe) {
        size_t i = ((size_t)(b - bte) * 256 + threadIdx.x) * 8;
        if (i < (size_t)N_ENT * DIM) {
            float4 f0 = *reinterpret_cast<const float4*>(entf + i);
            float4 f1 = *reinterpret_cast<const float4*>(entf + i + 4);
            __half h[8];
            h[0] = __float2half_rn(f0.x); h[1] = __float2half_rn(f0.y);
            h[2] = __float2half_rn(f0.z); h[3] = __float2half_rn(f0.w);
            h[4] = __float2half_rn(f1.x); h[5] = __float2half_rn(f1.y);
            h[6] = __float2half_rn(f1.z); h[7] = __float2half_rn(f1.w);
            *reinterpret_cast<uint4*>(&g_entf16[i]) = *reinterpret_cast<uint4*>(h);
        }
    } else {
        size_t i = ((size_t)(b - bfe) * 256 + threadIdx.x) * 8;
        if (i < (size_t)N_TOP * DIM) {
            float4 f0 = *reinterpret_cast<const float4*>(topf + i);
            float4 f1 = *reinterpret_cast<const float4*>(topf + i + 4);
            __half h[8];
            h[0] = __float2half_rn(f0.x); h[1] = __float2half_rn(f0.y);
            h[2] = __float2half_rn(f0.z); h[3] = __float2half_rn(f0.w);
            h[4] = __float2half_rn(f1.x); h[5] = __float2half_rn(f1.y);
            h[6] = __float2half_rn(f1.z); h[7] = __float2half_rn(f1.w);
            *reinterpret_cast<uint4*>(&g_topf16[i]) = *reinterpret_cast<uint4*>(h);
        }
    }
}

// ==================== launches 2-3: parallel scan ==========================
__global__ void scan1_kernel() {
    __shared__ int sh[256];
    int t = threadIdx.x, b = blockIdx.x;
    int base = b * 1024 + t * 4;
    int v0 = 0, v1 = 0, v2 = 0, v3 = 0;
    if (base + 0 < NTOT2) { v0 = g_cnt[base + 0]; g_deg[base + 0] = v0; }
    if (base + 1 < NTOT2) { v1 = g_cnt[base + 1]; g_deg[base + 1] = v1; }
    if (base + 2 < NTOT2) { v2 = g_cnt[base + 2]; g_deg[base + 2] = v2; }
    if (base + 3 < NTOT2) { v3 = g_cnt[base + 3]; g_deg[base + 3] = v3; }
    sh[t] = v0 + v1 + v2 + v3;
    __syncthreads();
    #pragma unroll
    for (int off = 1; off < 256; off <<= 1) {
        int x = 0;
        if (t >= off) x = sh[t - off];
        __syncthreads();
        if (t >= off) sh[t] += x;
        __syncthreads();
    }
    int run = (t > 0) ? sh[t - 1] : 0;
    if (base + 0 < NTOT2) g_rowstart[base + 0] = run; run += v0;
    if (base + 1 < NTOT2) g_rowstart[base + 1] = run; run += v1;
    if (base + 2 < NTOT2) g_rowstart[base + 2] = run; run += v2;
    if (base + 3 < NTOT2) g_rowstart[base + 3] = run;
    if (t == 255) g_bsum[b] = sh[255];
}

// scan3: redundant block-sum scan per block + offsets + cnt reset
__global__ void scan3_kernel() {
    __shared__ int sh[256];
    int t = threadIdx.x;
    int v = (t < SCAN_BLOCKS) ? g_bsum[t] : 0;
    sh[t] = v;
    __syncthreads();
    #pragma unroll
    for (int off = 1; off < 256; off <<= 1) {
        int x = 0;
        if (t >= off) x = sh[t - off];
        __syncthreads();
        if (t >= off) sh[t] += x;
        __syncthreads();
    }
    int i = blockIdx.x * blockDim.x + t;
    if (i < NTOT2) {
        int bb = i >> 10;
        int off = (bb > 0) ? sh[bb - 1] : 0;
        g_rowstart[i] = g_rowstart[i] + off;
        g_cnt[i] = 0;
    }
}

// ==================== launch 4: fill (atomic-free, rank-based) =============
__device__ __forceinline__ void fill_batch(const int* __restrict__ row,
                                           const int* __restrict__ col,
                                           const int* __restrict__ rank,
                                           int n, int cbase, int blk) {
    int base = blk * 1024 + threadIdx.x;
    int r[4], cc[4], rk[4], rs[4];
    #pragma unroll
    for (int s = 0; s < 4; s++) {
        int i = base + s * 256;
        if (i < n) { r[s] = row[i]; cc[s] = col[i]; rk[s] = rank[i]; }
        else r[s] = -1;
    }
    #pragma unroll
    for (int s = 0; s < 4; s++)
        if (r[s] >= 0) rs[s] = g_rowstart[cbase + r[s]];
    #pragma unroll
    for (int s = 0; s < 4; s++)
        if (r[s] >= 0) g_csr_col[rs[s] + rk[s]] = cc[s];
}

__global__ void fill_both_kernel(const int* __restrict__ ent_row,
                                 const int* __restrict__ ent_col, int n_ent,
                                 const int* __restrict__ top_row,
                                 const int* __restrict__ top_col, int n_top,
                                 int be) {
    int b = blockIdx.x;
    if (b < be)
        fill_batch(ent_row, ent_col, g_rank, n_ent, 0, b);
    else
        fill_batch(top_row, top_col, g_rank + MAX_EDGES, n_top, N_NEWS, b - be);
}

// ==================== launch 5: gather (one warp per news row) =============
__device__ __forceinline__ void store_h4(int r, int colb, float4 v) {
    __half h[4];
    h[0] = __float2half_rn(v.x);
    h[1] = __float2half_rn(v.y);
    h[2] = __float2half_rn(v.z);
    h[3] = __float2half_rn(v.w);
    *reinterpret_cast<uint2*>(&g_X[(size_t)r * KDIM + colb]) =
        *reinterpret_cast<uint2*>(h);
}

__device__ __forceinline__ void agg_part16(const __half* __restrict__ feats,
                                           int s, int c, int r, int colb,
                                           int lane) {
    float a0 = 0.f, a1 = 0.f, a2 = 0.f, a3 = 0.f;
    const uint2* f2 = reinterpret_cast<const uint2*>(feats);
    int j = 0;
    for (; j + 4 <= c; j += 4) {
        int c0 = g_csr_col[s + j];
        int c1 = g_csr_col[s + j + 1];
        int c2 = g_csr_col[s + j + 2];
        int c3 = g_csr_col[s + j + 3];
        uint2 u0 = f2[(size_t)c0 * 32 + lane];
        uint2 u1 = f2[(size_t)c1 * 32 + lane];
        uint2 u2 = f2[(size_t)c2 * 32 + lane];
        uint2 u3 = f2[(size_t)c3 * 32 + lane];
        __half2 s0 = __hadd2(*reinterpret_cast<__half2*>(&u0.x),
                             *reinterpret_cast<__half2*>(&u1.x));
        __half2 s1 = __hadd2(*reinterpret_cast<__half2*>(&u0.y),
                             *reinterpret_cast<__half2*>(&u1.y));
        __half2 s2 = __hadd2(*reinterpret_cast<__half2*>(&u2.x),
                             *reinterpret_cast<__half2*>(&u3.x));
        __half2 s3 = __hadd2(*reinterpret_cast<__half2*>(&u2.y),
                             *reinterpret_cast<__half2*>(&u3.y));
        float2 p0 = __half22float2(s0);
        float2 p1 = __half22float2(s1);
        float2 q0 = __half22float2(s2);
        float2 q1 = __half22float2(s3);
        a0 += p0.x + q0.x; a1 += p0.y + q0.y;
        a2 += p1.x + q1.x; a3 += p1.y + q1.y;
    }
    if (j + 2 <= c) {
        int c0 = g_csr_col[s + j];
        int c1 = g_csr_col[s + j + 1];
        uint2 u0 = f2[(size_t)c0 * 32 + lane];
        uint2 u1 = f2[(size_t)c1 * 32 + lane];
        __half2 s0 = __hadd2(*reinterpret_cast<__half2*>(&u0.x),
                             *reinterpret_cast<__half2*>(&u1.x));
        __half2 s1 = __hadd2(*reinterpret_cast<__half2*>(&u0.y),
                             *reinterpret_cast<__half2*>(&u1.y));
        float2 p0 = __half22float2(s0);
        float2 p1 = __half22float2(s1);
        a0 += p0.x; a1 += p0.y; a2 += p1.x; a3 += p1.y;
        j += 2;
    }
    if (j < c) {
        int c0 = g_csr_col[s + j];
        uint2 u0 = f2[(size_t)c0 * 32 + lane];
        float2 p0 = __half22float2(*reinterpret_cast<__half2*>(&u0.x));
        float2 p1 = __half22float2(*reinterpret_cast<__half2*>(&u0.y));
        a0 += p0.x; a1 += p0.y; a2 += p1.x; a3 += p1.y;
    }
    float inv = 1.0f / ((float)c + 1e-8f);
    float4 v = make_float4(a0 * inv, a1 * inv, a2 * inv, a3 * inv);
    store_h4(r, colb, v);
}

__global__ __launch_bounds__(256) void gather_kernel(
    const float* __restrict__ news) {
    int gw   = (blockIdx.x * blockDim.x + threadIdx.x) >> 5;
    int lane = threadIdx.x & 31;
    if (gw >= N_NEWS) return;
    float4 v = reinterpret_cast<const float4*>(news)[(size_t)gw * 32 + lane];
    store_h4(gw, lane * 4, v);
    agg_part16(g_entf16, g_rowstart[gw], g_deg[gw], gw, 128 + lane * 4, lane);
    agg_part16(g_topf16, g_rowstart[N_NEWS + gw], g_deg[N_NEWS + gw], gw,
               256 + lane * 4, lane);
}

// ==================== GEMM: cp.async 2-stage, K64, fp16xfp16 ===============
#define TILE_BYTES 16384
#define STAGE_B    (2 * TILE_BYTES)
#define GEMM_SMEM  (2 * STAGE_B)

template <bool TANH, bool HALF_OUT>
__global__ __launch_bounds__(256, 2) void gemm_mma_kernel(
    const __half* __restrict__ A, const __half* __restrict__ Bh,
    const float* __restrict__ bias,
    float* __restrict__ outF, __half* __restrict__ outH,
    int M, int Ntot, int Kfull) {
    extern __shared__ __align__(1024) char smem[];
    const uint32_t sbase = smem_to_u32(smem);

    const int tid  = threadIdx.x;
    const int wid  = tid >> 5;
    const int lane = tid & 31;
    const int wm   = wid & 1;
    const int wn   = wid >> 1;
    const int m0   = blockIdx.y * 128;
    const int n0   = blockIdx.x * 128;

    float acc[4][4][4] = {};

    const int lrow = tid >> 1;
    const int lseg = (tid & 1) * 4;
    const int gr   = m0 + lrow;
    const int a_ok = gr < M;
    const size_t a_base = (size_t)gr * Kfull + lseg * 8;
    const size_t b_base = (size_t)(n0 + lrow) * Kfull + lseg * 8;

    const int a_row = (lane & 7) + ((lane >> 3) & 1) * 8;
    const int a_ch  = lane >> 4;
    const int b_row = (lane & 7) + ((lane >> 4) & 1) * 8;
    const int b_ch  = (lane >> 3) & 1;

    const int n_chunks = Kfull >> 6;

    auto prefetch = [&](int ch) {
        const int k0 = ch << 6;
        const uint32_t sb = sbase + (ch & 1) * STAGE_B;
        const __half* pa = A + a_base + k0;
        const __half* pb = Bh + b_base + k0;
        #pragma unroll
        for (int s = 0; s < 4; s++) {
            uint32_t so = sw_off(lrow, lseg + s);
            cpa16(sb + so,              pa + s * 8, a_ok);
            cpa16(sb + TILE_BYTES + so, pb + s * 8, 1);
        }
        CP_COMMIT();
    };

    prefetch(0);
    for (int ch = 0; ch < n_chunks; ch++) {
        if (ch + 1 < n_chunks) {
            prefetch(ch + 1);
            CP_WAIT(1);
        } else {
            CP_WAIT(0);
        }
        __syncthreads();

        const uint32_t st = sbase + (ch & 1) * STAGE_B;
        #pragma unroll
        for (int kk = 0; kk < 4; kk++) {
            uint32_t afrag[4][4];
            uint32_t bhf[2][4];
            #pragma unroll
            for (int g2 = 0; g2 < 2; g2++) {
                int nr = wn * 32 + g2 * 16 + b_row;
                ldsm_x4(bhf[g2], st + TILE_BYTES + sw_off(nr, 2 * kk + b_ch));
            }
            #pragma unroll
            for (int mi = 0; mi < 4; mi++) {
                int mr = wm * 64 + mi * 16 + a_row;
                ldsm_x4(afrag[mi], st + sw_off(mr, 2 * kk + a_ch));
            }
            #pragma unroll
            for (int mi = 0; mi < 4; mi++)
                #pragma unroll
                for (int ni = 0; ni < 4; ni++)
                    mma_fp16(acc[mi][ni], afrag[mi],
                             &bhf[ni >> 1][(ni & 1) * 2]);
        }
        __syncthreads();
    }

    const int g = lane >> 2;
    const int q = lane & 3;
    #pragma unroll
    for (int mi = 0; mi < 4; mi++) {
        #pragma unroll
        for (int ni = 0; ni < 4; ni++) {
            int col = n0 + wn * 32 + ni * 8 + q * 2;
            float bia0 = bias[col], bia1 = bias[col + 1];
            #pragma unroll
            for (int half = 0; half < 2; half++) {
                int gm = m0 + wm * 64 + mi * 16 + g + half * 8;
                if (gm >= M) continue;
                float v0 = acc[mi][ni][half * 2 + 0] + bia0;
                float v1 = acc[mi][ni][half * 2 + 1] + bia1;
                if (TANH) { v0 = tanhf(v0); v1 = tanhf(v1); }
                size_t o = (size_t)gm * Ntot + col;
                if (HALF_OUT) {
                    *reinterpret_cast<__half2*>(&outH[o]) =
                        __halves2half2(__float2half_rn(v0), __float2half_rn(v1));
                } else {
                    *reinterpret_cast<float2*>(&outF[o]) = make_float2(v0, v1);
                }
            }
        }
    }
}

// ---------------------------------------------------------------------------
extern "C" void kernel_launch(void* const* d_in, const int* in_sizes, int n_in,
                              void* d_out, int out_size) {
    const float* news    = (const float*)d_in[0];
    const float* entf    = (const float*)d_in[1];
    const float* topf    = (const float*)d_in[2];
    const int*   ent_row = (const int*)d_in[3];
    const int*   ent_col = (const int*)d_in[4];
    const int*   top_row = (const int*)d_in[5];
    const int*   top_col = (const int*)d_in[6];
    const float* W1      = (const float*)d_in[7];
    const float* b1      = (const float*)d_in[8];
    const float* W2      = (const float*)d_in[9];
    const float* b2      = (const float*)d_in[10];
    float* out = (float*)d_out;
    int n_ent = in_sizes[3];
    int n_top = in_sizes[5];

    void *p_x, *p_h, *p_w1, *p_w2;
    cudaGetSymbolAddress(&p_x, g_X);
    cudaGetSymbolAddress(&p_h, g_H);
    cudaGetSymbolAddress(&p_w1, g_W1t);
    cudaGetSymbolAddress(&p_w2, g_W2t);

    cudaFuncSetAttribute(gemm_mma_kernel<true, true>,
                         cudaFuncAttributeMaxDynamicSharedMemorySize, GEMM_SMEM);
    cudaFuncSetAttribute(gemm_mma_kernel<false, false>,
                         cudaFuncAttributeMaxDynamicSharedMemorySize, GEMM_SMEM);

    // launch 1: setup (weight prep + hist-with-rank + fp16 feature convert)
    {
        int b1e = (KDIM * HIDN + 255) / 256;
        int b2e = b1e + (HIDN * OUTD + 255) / 256;
        int bhe = b2e + (n_ent + 255) / 256;
        int bte = bhe + (n_top + 255) / 256;
        int bfe = bte + (N_ENT * DIM / 8 + 255) / 256;
        int btot = bfe + (N_TOP * DIM / 8 + 255) / 256;
        setup_kernel<<<btot, 256>>>(W1, W2, ent_row, n_ent, top_row, n_top,
                                    entf, topf, b1e, b2e, bhe, bte, bfe);
    }
    // launches 2-3: parallel scan
    scan1_kernel<<<SCAN_BLOCKS, 256>>>();
    scan3_kernel<<<(NTOT2 + 255) / 256, 256>>>();
    // launch 4: fill (atomic-free)
    {
        int be = (n_ent + 1023) / 1024;
        int btot = be + (n_top + 1023) / 1024;
        fill_both_kernel<<<btot, 256>>>(ent_row, ent_col, n_ent,
                                        top_row, top_col, n_top, be);
    }
    // launch 5: gather -> X (fp16)
    {
        int blocks = (N_NEWS * 32 + 255) / 256;
        gather_kernel<<<blocks, 256>>>(news);
    }

    const int m_tiles = (N_NEWS + 127) / 128;  // 782

    // launch 6: GEMM1  H = tanh(X @ W1 + b1)
    {
        dim3 grid(HIDN / 128, m_tiles);
        gemm_mma_kernel<true, true><<<grid, 256, GEMM_SMEM>>>(
            (const __half*)p_x, (const __half*)p_w1,
            b1, nullptr, (__half*)p_h,
            N_NEWS, HIDN, KDIM);
    }
    // launch 7: GEMM2  out = H @ W2 + b2
    {
        dim3 grid(OUTD / 128, m_tiles);
        gemm_mma_kernel<false, false><<<grid, 256, GEMM_SMEM>>>(
            (const __half*)p_h, (const __half*)p_w2,
            b2, out, nullptr,
            N_NEWS, OUTD, HIDN);
    }
}